// round 13
// baseline (speedup 1.0000x reference)
#include <cuda_runtime.h>
#include <math.h>

#define NPTS 8192
#define CF   64
#define NH   4
#define KNN  16
#define DHD  16
#define TILE 1024
#define PPB  2

#define FINF 3.402823466e38f
#define FULLM 0xffffffffu

#define PACK2(out, lo, hi) \
    asm("mov.b64 %0, {%1, %2};" : "=l"(out) : "r"(lo), "r"(hi))
#define UNPACK2(lo, hi, in) \
    asm("mov.b64 {%0, %1}, %2;" : "=r"(lo), "=r"(hi) : "l"(in))
#define FMA2(d, a, b, c) \
    asm("fma.rn.f32x2 %0, %1, %2, %3;" : "=l"(d) : "l"(a), "l"(b), "l"(c))

// ---------------- scratch (static device memory; no allocations) -------------
__device__ float g_xq[NPTS * CF];
__device__ float g_xk[NPTS * CF];
__device__ float g_xv[NPTS * CF];
__device__ int   g_idx[NPTS * KNN];

// ---------------- KNN: warp-cooperative, 2 queries/warp, sorted top-16 -------
// f32x2-packed distances; events dispatched per hit-LANE (broadcast its 4
// slot metrics, insert the survivors) instead of per-slot ballots.
// Slot u covers candidate  tile + j0 + ((u>>1)<<6) + 2*lane + (u&1).
__global__ void __launch_bounds__(256)
knn_kernel(const float* __restrict__ p) {
    __shared__ __align__(16) ulonglong2 sxy[TILE / 2];
    __shared__ __align__(16) ulonglong2 szw[TILE / 2];
    const int lane  = threadIdx.x & 31;
    const int warp  = threadIdx.x >> 5;
    const int qbase = (blockIdx.x * 8 + warp) * 2;

    const float aX = -2.0f * p[3 * qbase + 0];
    const float aY = -2.0f * p[3 * qbase + 1];
    const float aZ = -2.0f * p[3 * qbase + 2];
    const float bX = -2.0f * p[3 * qbase + 3];
    const float bY = -2.0f * p[3 * qbase + 4];
    const float bZ = -2.0f * p[3 * qbase + 5];

    unsigned long long aX2, aY2, aZ2, bX2, bY2, bZ2;
    PACK2(aX2, __float_as_uint(aX), __float_as_uint(aX));
    PACK2(aY2, __float_as_uint(aY), __float_as_uint(aY));
    PACK2(aZ2, __float_as_uint(aZ), __float_as_uint(aZ));
    PACK2(bX2, __float_as_uint(bX), __float_as_uint(bX));
    PACK2(bY2, __float_as_uint(bY), __float_as_uint(bY));
    PACK2(bZ2, __float_as_uint(bZ), __float_as_uint(bZ));

    // ---- seed: top-16 from candidates 0..15 via 16-lane bitonic sort ----
    float best_d;
    int   best_i;
    float thrA, thrB;
    {
        const int pos = lane & 15;
        float x = p[3 * pos + 0], y = p[3 * pos + 1], z = p[3 * pos + 2];
        float w = fmaf(x, x, fmaf(y, y, z * z));
        float d = (lane < 16)
                ? fmaf(aX, x, fmaf(aY, y, fmaf(aZ, z, w)))
                : fmaf(bX, x, fmaf(bY, y, fmaf(bZ, z, w)));
        int i = pos;
#pragma unroll
        for (int k = 2; k <= 16; k <<= 1) {
#pragma unroll
            for (int j = k >> 1; j >= 1; j >>= 1) {
                float od = __shfl_xor_sync(FULLM, d, j);
                int   oi = __shfl_xor_sync(FULLM, i, j);
                bool lower = (pos & j) == 0;
                bool asc   = (pos & k) == 0;
                bool takeOther = (lower == asc) ? (od < d) : (od > d);
                if (takeOther) { d = od; i = oi; }
            }
        }
        best_d = d;
        best_i = i;
        thrA = __shfl_sync(FULLM, best_d, 15);
        thrB = __shfl_sync(FULLM, best_d, 31);
    }

    for (int tile = 0; tile < NPTS; tile += TILE) {
        __syncthreads();
        for (int i = threadIdx.x; i < TILE / 2; i += 256) {
            const float* pc = p + 3 * (tile + 2 * i);
            float x0 = pc[0], y0 = pc[1], z0 = pc[2];
            float x1 = pc[3], y1 = pc[4], z1 = pc[5];
            float w0 = fmaf(x0, x0, fmaf(y0, y0, z0 * z0));
            float w1 = fmaf(x1, x1, fmaf(y1, y1, z1 * z1));
            unsigned long long xp, yp, zp, wp;
            PACK2(xp, __float_as_uint(x0), __float_as_uint(x1));
            PACK2(yp, __float_as_uint(y0), __float_as_uint(y1));
            PACK2(zp, __float_as_uint(z0), __float_as_uint(z1));
            PACK2(wp, __float_as_uint(w0), __float_as_uint(w1));
            sxy[i] = make_ulonglong2(xp, yp);
            szw[i] = make_ulonglong2(zp, wp);
        }
        __syncthreads();

        for (int j0 = 0; j0 < TILE; j0 += 128) {
            const int jh = j0 >> 1;
            ulonglong2 u0 = sxy[jh + lane];
            ulonglong2 v0 = szw[jh + lane];
            ulonglong2 u1 = sxy[jh + 32 + lane];
            ulonglong2 v1 = szw[jh + 32 + lane];

            // t = w - 2 q.p  (packed over candidate pairs)
            unsigned long long tApk0, tApk1, tBpk0, tBpk1, t0, t1, t2, t3;
            FMA2(t0, aZ2, v0.x, v0.y);
            FMA2(t0, aY2, u0.y, t0);
            FMA2(tApk0, aX2, u0.x, t0);
            FMA2(t1, aZ2, v1.x, v1.y);
            FMA2(t1, aY2, u1.y, t1);
            FMA2(tApk1, aX2, u1.x, t1);
            FMA2(t2, bZ2, v0.x, v0.y);
            FMA2(t2, bY2, u0.y, t2);
            FMA2(tBpk0, bX2, u0.x, t2);
            FMA2(t3, bZ2, v1.x, v1.y);
            FMA2(t3, bY2, u1.y, t3);
            FMA2(tBpk1, bX2, u1.x, t3);

            float tA[4], tB[4];
            {
                unsigned lo, hi;
                UNPACK2(lo, hi, tApk0); tA[0] = __uint_as_float(lo); tA[1] = __uint_as_float(hi);
                UNPACK2(lo, hi, tApk1); tA[2] = __uint_as_float(lo); tA[3] = __uint_as_float(hi);
                UNPACK2(lo, hi, tBpk0); tB[0] = __uint_as_float(lo); tB[1] = __uint_as_float(hi);
                UNPACK2(lo, hi, tBpk1); tB[2] = __uint_as_float(lo); tB[3] = __uint_as_float(hi);
            }

            // candidates 0..15 already seeded — they map to lanes 0..7, slots 0/1
            if ((tile | j0) == 0 && lane < 8) {
                tA[0] = FINF; tA[1] = FINF;
                tB[0] = FINF; tB[1] = FINF;
            }

            float mA = fminf(fminf(tA[0], tA[1]), fminf(tA[2], tA[3]));
            float mB = fminf(fminf(tB[0], tB[1]), fminf(tB[2], tB[3]));

            unsigned hitA = __ballot_sync(FULLM, mA < thrA);
            unsigned hitB = __ballot_sync(FULLM, mB < thrB);

            // ---- query A events: dispatch per hit lane ----
            while (hitA) {
                const int hl = __ffs(hitA) - 1;
                hitA &= hitA - 1;
                float cv0 = __shfl_sync(FULLM, tA[0], hl);
                float cv1 = __shfl_sync(FULLM, tA[1], hl);
                float cv2 = __shfl_sync(FULLM, tA[2], hl);
                float cv3 = __shfl_sync(FULLM, tA[3], hl);
                const float cv[4] = {cv0, cv1, cv2, cv3};
#pragma unroll
                for (int u = 0; u < 4; u++) {
                    const float dn = cv[u];
                    if (dn < thrA) {                    // uniform branch
                        unsigned lt = __ballot_sync(FULLM, best_d < dn);
                        const int r = __popc(lt & 0xFFFFu);
                        float pd = __shfl_up_sync(FULLM, best_d, 1);
                        int   pi = __shfl_up_sync(FULLM, best_i, 1);
                        if (lane < 16) {
                            if (lane == r) {
                                best_d = dn;
                                best_i = tile + j0 + ((u >> 1) << 6) + (u & 1) + 2 * hl;
                            } else if (lane > r) { best_d = pd; best_i = pi; }
                        }
                        thrA = __shfl_sync(FULLM, best_d, 15);
                    }
                }
            }
            // ---- query B events: dispatch per hit lane ----
            while (hitB) {
                const int hl = __ffs(hitB) - 1;
                hitB &= hitB - 1;
                float cv0 = __shfl_sync(FULLM, tB[0], hl);
                float cv1 = __shfl_sync(FULLM, tB[1], hl);
                float cv2 = __shfl_sync(FULLM, tB[2], hl);
                float cv3 = __shfl_sync(FULLM, tB[3], hl);
                const float cv[4] = {cv0, cv1, cv2, cv3};
#pragma unroll
                for (int u = 0; u < 4; u++) {
                    const float dn = cv[u];
                    if (dn < thrB) {                    // uniform branch
                        unsigned lt = __ballot_sync(FULLM, best_d < dn);
                        const int r = __popc(lt >> 16);
                        float pd = __shfl_up_sync(FULLM, best_d, 1);
                        int   pi = __shfl_up_sync(FULLM, best_i, 1);
                        const int pos = lane - 16;
                        if (pos >= 0) {
                            if (pos == r) {
                                best_d = dn;
                                best_i = tile + j0 + ((u >> 1) << 6) + (u & 1) + 2 * hl;
                            } else if (pos > r) { best_d = pd; best_i = pi; }
                        }
                        thrB = __shfl_sync(FULLM, best_d, 31);
                    }
                }
            }
        }
    }
    const int q = qbase + (lane >> 4);
    g_idx[q * KNN + (lane & 15)] = best_i;
}

// ---------------- xq/xk/xv = x @ {Wq,Wk,Wv} ---------------------------------
__global__ void __launch_bounds__(256)
qkv_gemm_kernel(const float* __restrict__ x,
                const float* __restrict__ Wq,
                const float* __restrict__ Wk,
                const float* __restrict__ Wv) {
    __shared__ __align__(16) float Ws[CF * CF];
    __shared__ __align__(16) float xs[CF * CF];
    const float* W = (blockIdx.y == 0) ? Wq : ((blockIdx.y == 1) ? Wk : Wv);
    float* out = (blockIdx.y == 0) ? g_xq : ((blockIdx.y == 1) ? g_xk : g_xv);

    const int row0 = blockIdx.x * 64;
    const int tid  = threadIdx.y * 64 + threadIdx.x;
    for (int f = tid; f < CF * CF; f += 256) {
        Ws[f] = W[f];
        xs[f] = x[row0 * CF + f];
    }
    __syncthreads();

    const int c  = threadIdx.x;
    const int r0 = threadIdx.y * 16;
    float acc[16];
#pragma unroll
    for (int r = 0; r < 16; r++) acc[r] = 0.0f;

    const float4* xsv = reinterpret_cast<const float4*>(xs);
    for (int j4 = 0; j4 < 16; j4++) {
        float w0 = Ws[(4 * j4 + 0) * CF + c];
        float w1 = Ws[(4 * j4 + 1) * CF + c];
        float w2 = Ws[(4 * j4 + 2) * CF + c];
        float w3 = Ws[(4 * j4 + 3) * CF + c];
#pragma unroll
        for (int r = 0; r < 16; r++) {
            float4 xv = xsv[(r0 + r) * 16 + j4];
            acc[r] = fmaf(xv.x, w0, acc[r]);
            acc[r] = fmaf(xv.y, w1, acc[r]);
            acc[r] = fmaf(xv.z, w2, acc[r]);
            acc[r] = fmaf(xv.w, w3, acc[r]);
        }
    }
#pragma unroll
    for (int r = 0; r < 16; r++) out[(row0 + r0 + r) * CF + c] = acc[r];
}

// ---------------- PPF angle helper ------------------------------------------
__device__ __forceinline__ float angle3(float ux, float uy, float uz,
                                        float vx, float vy, float vz) {
    float cx = uy * vz - uz * vy;
    float cy = uz * vx - ux * vz;
    float cz = ux * vy - uy * vx;
    float cn = sqrtf(cx * cx + cy * cy + cz * cz + 1e-9f);
    float dt = ux * vx + uy * vy + uz * vz;
    return atan2f(cn, dt);
}

// ---------------- Fused: PPF -> pe MLP -> attention -> Wo -> LN -> relu ------
// 2 points per block, 128 threads. pe1 stored transposed for f32x2 pe2.
__global__ void __launch_bounds__(128, 8)
fused_attn_kernel(const float* __restrict__ p,
                  const float* __restrict__ x,
                  const float* __restrict__ normals,
                  const float* __restrict__ Wo,
                  const float* __restrict__ w1, const float* __restrict__ b1,
                  const float* __restrict__ w2, const float* __restrict__ b2,
                  const float* __restrict__ ln_g, const float* __restrict__ ln_b,
                  float* __restrict__ out) {
    const int t128 = threadIdx.x;
    const int pt   = t128 >> 6;
    const int tid  = t128 & 63;
    const int n    = blockIdx.x * PPB + pt;

    __shared__ int   idx_s[PPB][KNN];
    __shared__ __align__(16) float ppf_s[PPB][KNN][4];
    __shared__ __align__(16) float pe1t[PPB][CF][KNN];   // transposed, 64B rows
    __shared__ __align__(16) float k_s[PPB][KNN][CF];
    __shared__ __align__(16) float v_s[PPB][KNN][CF];
    __shared__ __align__(16) float q_s[PPB][CF];
    __shared__ __align__(16) float o_s[PPB][CF];
    __shared__ float attn_s[PPB][NH * KNN];
    __shared__ float red_s[4][2];

    if (tid < KNN) idx_s[pt][tid] = g_idx[n * KNN + tid];
    q_s[pt][tid] = g_xq[n * CF + tid];
    __syncthreads();

    // PPF features: 64 tasks per point = (neighbor k, feature which)
    {
        const int k     = tid & 15;
        const int which = tid >> 4;
        const int j = idx_s[pt][k];
        float px = p[3 * n], py = p[3 * n + 1], pz = p[3 * n + 2];
        float dx = p[3 * j] - px, dy = p[3 * j + 1] - py, dz = p[3 * j + 2] - pz;
        float ncx = normals[3 * n], ncy = normals[3 * n + 1], ncz = normals[3 * n + 2];
        float nrx = normals[3 * j], nry = normals[3 * j + 1], nrz = normals[3 * j + 2];
        float ux = (which == 1) ? nrx : ncx;
        float uy = (which == 1) ? nry : ncy;
        float uz = (which == 1) ? nrz : ncz;
        float vx = (which == 2) ? nrx : dx;
        float vy = (which == 2) ? nry : dy;
        float vz = (which == 2) ? nrz : dz;
        float a = angle3(ux, uy, uz, vx, vy, vz);
        float dist = sqrtf(fmaf(dx, dx, fmaf(dy, dy, dz * dz)) + 1e-9f);
        ppf_s[pt][k][which] = (which == 3) ? dist : a;
    }
    __syncthreads();

    // pe layer 1, written transposed: pe1t[tid][k] (k rotated to soften conflicts)
    {
        float w0 = __ldg(&w1[0 * CF + tid]);
        float wa = __ldg(&w1[1 * CF + tid]);
        float wb = __ldg(&w1[2 * CF + tid]);
        float wc = __ldg(&w1[3 * CF + tid]);
        float bb = __ldg(&b1[tid]);
#pragma unroll
        for (int i = 0; i < KNN; i++) {
            const int k = (i + tid) & 15;
            float4 pf = *reinterpret_cast<const float4*>(&ppf_s[pt][k][0]);
            float v = bb;
            v = fmaf(pf.x, w0, v);
            v = fmaf(pf.y, wa, v);
            v = fmaf(pf.z, wb, v);
            v = fmaf(pf.w, wc, v);
            pe1t[pt][tid][k] = fmaxf(v, 0.0f);
        }
    }
    __syncthreads();

    // pe layer 2 on packed f32x2: acc2[m] covers neighbors (2m, 2m+1)
    {
        unsigned long long acc2[8];
        {
            float bb2 = __ldg(&b2[tid]);
            unsigned bbu = __float_as_uint(bb2);
            unsigned long long bp;
            PACK2(bp, bbu, bbu);
#pragma unroll
            for (int m = 0; m < 8; m++) acc2[m] = bp;
        }
#pragma unroll 4
        for (int j = 0; j < CF; j++) {
            float w = __ldg(&w2[j * CF + tid]);
            unsigned wu = __float_as_uint(w);
            unsigned long long wp;
            PACK2(wp, wu, wu);
            const ulonglong2* row =
                reinterpret_cast<const ulonglong2*>(&pe1t[pt][j][0]);
#pragma unroll
            for (int pp = 0; pp < 4; pp++) {
                ulonglong2 r2 = row[pp];
                FMA2(acc2[2 * pp + 0], r2.x, wp, acc2[2 * pp + 0]);
                FMA2(acc2[2 * pp + 1], r2.y, wp, acc2[2 * pp + 1]);
            }
        }
        // unpack + gather xk/xv, build k/v tiles
#pragma unroll
        for (int m = 0; m < 8; m++) {
            unsigned lo, hi;
            UNPACK2(lo, hi, acc2[m]);
            float a0 = __uint_as_float(lo);
            float a1 = __uint_as_float(hi);
            const int k0 = 2 * m, k1 = 2 * m + 1;
            const int j0 = idx_s[pt][k0];
            const int j1 = idx_s[pt][k1];
            k_s[pt][k0][tid] = g_xk[j0 * CF + tid] + a0;
            v_s[pt][k0][tid] = g_xv[j0 * CF + tid] + a0;
            k_s[pt][k1][tid] = g_xk[j1 * CF + tid] + a1;
            v_s[pt][k1][tid] = g_xv[j1 * CF + tid] + a1;
        }
    }
    __syncthreads();

    // attention: thread = (head h, neighbor kk) within its point
    {
        const int h  = tid >> 4;
        const int kk = tid & 15;
        float logit = 0.0f;
        const float4* kv = reinterpret_cast<const float4*>(&k_s[pt][kk][h * DHD]);
        const float4* qv = reinterpret_cast<const float4*>(&q_s[pt][h * DHD]);
#pragma unroll
        for (int d4 = 0; d4 < 4; d4++) {
            float4 kq = kv[d4];
            float4 qq = qv[d4];
            logit = fmaf(qq.x, kq.x, logit);
            logit = fmaf(qq.y, kq.y, logit);
            logit = fmaf(qq.z, kq.z, logit);
            logit = fmaf(qq.w, kq.w, logit);
        }
        logit *= 0.25f;  // 1/sqrt(16)

        float m = logit;
#pragma unroll
        for (int s = 8; s >= 1; s >>= 1)
            m = fmaxf(m, __shfl_xor_sync(FULLM, m, s, 16));
        float e = __expf(logit - m);
        float ssum = e;
#pragma unroll
        for (int s = 8; s >= 1; s >>= 1)
            ssum += __shfl_xor_sync(FULLM, ssum, s, 16);
        attn_s[pt][tid] = e / ssum;
    }
    __syncthreads();

    // out[c] = sum_k attn[h][k] * v[k][c],  c = h*16 + d
    {
        float o = 0.0f;
        const int hb = tid & ~15;
#pragma unroll
        for (int k = 0; k < KNN; k++)
            o = fmaf(attn_s[pt][hb + k], v_s[pt][k][tid], o);
        o_s[pt][tid] = o;
    }
    __syncthreads();

    // y = o @ Wo
    float y = 0.0f;
    {
        const float4* ov = reinterpret_cast<const float4*>(&o_s[pt][0]);
        for (int j4 = 0; j4 < 16; j4++) {
            float4 o4 = ov[j4];
            y = fmaf(o4.x, __ldg(&Wo[(4 * j4 + 0) * CF + tid]), y);
            y = fmaf(o4.y, __ldg(&Wo[(4 * j4 + 1) * CF + tid]), y);
            y = fmaf(o4.z, __ldg(&Wo[(4 * j4 + 2) * CF + tid]), y);
            y = fmaf(o4.w, __ldg(&Wo[(4 * j4 + 3) * CF + tid]), y);
        }
    }

    // LayerNorm (biased var), residual, relu
    float s1 = y, s2 = y * y;
#pragma unroll
    for (int s = 16; s >= 1; s >>= 1) {
        s1 += __shfl_xor_sync(FULLM, s1, s);
        s2 += __shfl_xor_sync(FULLM, s2, s);
    }
    const int wrp = t128 >> 5;
    if ((t128 & 31) == 0) {
        red_s[wrp][0] = s1;
        red_s[wrp][1] = s2;
    }
    __syncthreads();
    float S1 = red_s[2 * pt][0] + red_s[2 * pt + 1][0];
    float S2 = red_s[2 * pt][1] + red_s[2 * pt + 1][1];
    float mu  = S1 * (1.0f / 64.0f);
    float var = S2 * (1.0f / 64.0f) - mu * mu;
    float nrm = (y - mu) * rsqrtf(var + 1e-5f);
    float res = fmaf(nrm, __ldg(&ln_g[tid]), __ldg(&ln_b[tid])) + x[n * CF + tid];
    out[n * CF + tid] = fmaxf(res, 0.0f);
}

// ---------------- launch -----------------------------------------------------
extern "C" void kernel_launch(void* const* d_in, const int* in_sizes, int n_in,
                              void* d_out, int out_size) {
    (void)in_sizes; (void)n_in; (void)out_size;
    const float* p       = (const float*)d_in[0];
    const float* x       = (const float*)d_in[1];
    const float* normals = (const float*)d_in[2];
    const float* Wq      = (const float*)d_in[3];
    const float* Wk      = (const float*)d_in[4];
    const float* Wv      = (const float*)d_in[5];
    const float* Wo      = (const float*)d_in[6];
    const float* w1      = (const float*)d_in[7];
    const float* b1      = (const float*)d_in[8];
    const float* w2      = (const float*)d_in[9];
    const float* b2      = (const float*)d_in[10];
    const float* ln_g    = (const float*)d_in[11];
    const float* ln_b    = (const float*)d_in[12];
    float* out = (float*)d_out;

    knn_kernel<<<NPTS / 16, 256>>>(p);
    qkv_gemm_kernel<<<dim3(NPTS / 64, 3), dim3(64, 4)>>>(x, Wq, Wk, Wv);
    fused_attn_kernel<<<NPTS / PPB, 128>>>(p, x, normals, Wo, w1, b1, w2, b2,
                                           ln_g, ln_b, out);
}

// round 14
// speedup vs baseline: 1.0827x; 1.0827x over previous
#include <cuda_runtime.h>
#include <math.h>

#define NPTS 8192
#define CF   64
#define NH   4
#define KNN  16
#define DHD  16
#define TILE 1024
#define PPB  2

#define FINF 3.402823466e38f
#define FULLM 0xffffffffu

#define PACK2(out, lo, hi) \
    asm("mov.b64 %0, {%1, %2};" : "=l"(out) : "r"(lo), "r"(hi))
#define UNPACK2(lo, hi, in) \
    asm("mov.b64 {%0, %1}, %2;" : "=r"(lo), "=r"(hi) : "l"(in))
#define FMA2(d, a, b, c) \
    asm("fma.rn.f32x2 %0, %1, %2, %3;" : "=l"(d) : "l"(a), "l"(b), "l"(c))

// ---------------- scratch (static device memory; no allocations) -------------
__device__ float g_xq[NPTS * CF];
__device__ float g_xk[NPTS * CF];
__device__ float g_xv[NPTS * CF];
__device__ int   g_idx[NPTS * KNN];

// ---------------- KNN: warp-cooperative, 2 queries/warp, sorted top-16 -------
// (R12 winner, byte-identical: f32x2 distances + per-slot fresh-ballot inserts)
__global__ void __launch_bounds__(256)
knn_kernel(const float* __restrict__ p) {
    __shared__ __align__(16) ulonglong2 sxy[TILE / 2];
    __shared__ __align__(16) ulonglong2 szw[TILE / 2];
    const int lane  = threadIdx.x & 31;
    const int warp  = threadIdx.x >> 5;
    const int qbase = (blockIdx.x * 8 + warp) * 2;

    const float aX = -2.0f * p[3 * qbase + 0];
    const float aY = -2.0f * p[3 * qbase + 1];
    const float aZ = -2.0f * p[3 * qbase + 2];
    const float bX = -2.0f * p[3 * qbase + 3];
    const float bY = -2.0f * p[3 * qbase + 4];
    const float bZ = -2.0f * p[3 * qbase + 5];

    unsigned long long aX2, aY2, aZ2, bX2, bY2, bZ2;
    PACK2(aX2, __float_as_uint(aX), __float_as_uint(aX));
    PACK2(aY2, __float_as_uint(aY), __float_as_uint(aY));
    PACK2(aZ2, __float_as_uint(aZ), __float_as_uint(aZ));
    PACK2(bX2, __float_as_uint(bX), __float_as_uint(bX));
    PACK2(bY2, __float_as_uint(bY), __float_as_uint(bY));
    PACK2(bZ2, __float_as_uint(bZ), __float_as_uint(bZ));

    // ---- seed: top-16 from candidates 0..15 via 16-lane bitonic sort ----
    float best_d;
    int   best_i;
    float thrA, thrB;
    {
        const int pos = lane & 15;
        float x = p[3 * pos + 0], y = p[3 * pos + 1], z = p[3 * pos + 2];
        float w = fmaf(x, x, fmaf(y, y, z * z));
        float d = (lane < 16)
                ? fmaf(aX, x, fmaf(aY, y, fmaf(aZ, z, w)))
                : fmaf(bX, x, fmaf(bY, y, fmaf(bZ, z, w)));
        int i = pos;
#pragma unroll
        for (int k = 2; k <= 16; k <<= 1) {
#pragma unroll
            for (int j = k >> 1; j >= 1; j >>= 1) {
                float od = __shfl_xor_sync(FULLM, d, j);
                int   oi = __shfl_xor_sync(FULLM, i, j);
                bool lower = (pos & j) == 0;
                bool asc   = (pos & k) == 0;
                bool takeOther = (lower == asc) ? (od < d) : (od > d);
                if (takeOther) { d = od; i = oi; }
            }
        }
        best_d = d;
        best_i = i;
        thrA = __shfl_sync(FULLM, best_d, 15);
        thrB = __shfl_sync(FULLM, best_d, 31);
    }

    for (int tile = 0; tile < NPTS; tile += TILE) {
        __syncthreads();
        for (int i = threadIdx.x; i < TILE / 2; i += 256) {
            const float* pc = p + 3 * (tile + 2 * i);
            float x0 = pc[0], y0 = pc[1], z0 = pc[2];
            float x1 = pc[3], y1 = pc[4], z1 = pc[5];
            float w0 = fmaf(x0, x0, fmaf(y0, y0, z0 * z0));
            float w1 = fmaf(x1, x1, fmaf(y1, y1, z1 * z1));
            unsigned long long xp, yp, zp, wp;
            PACK2(xp, __float_as_uint(x0), __float_as_uint(x1));
            PACK2(yp, __float_as_uint(y0), __float_as_uint(y1));
            PACK2(zp, __float_as_uint(z0), __float_as_uint(z1));
            PACK2(wp, __float_as_uint(w0), __float_as_uint(w1));
            sxy[i] = make_ulonglong2(xp, yp);
            szw[i] = make_ulonglong2(zp, wp);
        }
        __syncthreads();

        for (int j0 = 0; j0 < TILE; j0 += 128) {
            const int jh = j0 >> 1;
            ulonglong2 u0 = sxy[jh + lane];
            ulonglong2 v0 = szw[jh + lane];
            ulonglong2 u1 = sxy[jh + 32 + lane];
            ulonglong2 v1 = szw[jh + 32 + lane];

            unsigned long long tApk0, tApk1, tBpk0, tBpk1, t0, t1, t2, t3;
            FMA2(t0, aZ2, v0.x, v0.y);
            FMA2(t0, aY2, u0.y, t0);
            FMA2(tApk0, aX2, u0.x, t0);
            FMA2(t1, aZ2, v1.x, v1.y);
            FMA2(t1, aY2, u1.y, t1);
            FMA2(tApk1, aX2, u1.x, t1);
            FMA2(t2, bZ2, v0.x, v0.y);
            FMA2(t2, bY2, u0.y, t2);
            FMA2(tBpk0, bX2, u0.x, t2);
            FMA2(t3, bZ2, v1.x, v1.y);
            FMA2(t3, bY2, u1.y, t3);
            FMA2(tBpk1, bX2, u1.x, t3);

            float tA[4], tB[4];
            {
                unsigned lo, hi;
                UNPACK2(lo, hi, tApk0); tA[0] = __uint_as_float(lo); tA[1] = __uint_as_float(hi);
                UNPACK2(lo, hi, tApk1); tA[2] = __uint_as_float(lo); tA[3] = __uint_as_float(hi);
                UNPACK2(lo, hi, tBpk0); tB[0] = __uint_as_float(lo); tB[1] = __uint_as_float(hi);
                UNPACK2(lo, hi, tBpk1); tB[2] = __uint_as_float(lo); tB[3] = __uint_as_float(hi);
            }

            if ((tile | j0) == 0 && lane < 8) {
                tA[0] = FINF; tA[1] = FINF;
                tB[0] = FINF; tB[1] = FINF;
            }

            float mA = fminf(fminf(tA[0], tA[1]), fminf(tA[2], tA[3]));
            float mB = fminf(fminf(tB[0], tB[1]), fminf(tB[2], tB[3]));

            if (__any_sync(FULLM, (mA < thrA) | (mB < thrB))) {
#pragma unroll
                for (int u = 0; u < 4; u++) {
                    const int ubase = ((u >> 1) << 6) + (u & 1);
                    while (true) {
                        unsigned mask = __ballot_sync(FULLM, tA[u] < thrA);
                        if (!mask) break;
                        const int src = __ffs(mask) - 1;
                        const float dn = __shfl_sync(FULLM, tA[u], src);
                        if (lane == src) tA[u] = FINF;
                        unsigned lt = __ballot_sync(FULLM, best_d < dn);
                        const int r = __popc(lt & 0xFFFFu);
                        float pd = __shfl_up_sync(FULLM, best_d, 1);
                        int   pi = __shfl_up_sync(FULLM, best_i, 1);
                        if (lane < 16) {
                            if (lane == r)      { best_d = dn; best_i = tile + j0 + ubase + 2 * src; }
                            else if (lane > r)  { best_d = pd; best_i = pi; }
                        }
                        thrA = __shfl_sync(FULLM, best_d, 15);
                    }
                    while (true) {
                        unsigned mask = __ballot_sync(FULLM, tB[u] < thrB);
                        if (!mask) break;
                        const int src = __ffs(mask) - 1;
                        const float dn = __shfl_sync(FULLM, tB[u], src);
                        if (lane == src) tB[u] = FINF;
                        unsigned lt = __ballot_sync(FULLM, best_d < dn);
                        const int r = __popc(lt >> 16);
                        float pd = __shfl_up_sync(FULLM, best_d, 1);
                        int   pi = __shfl_up_sync(FULLM, best_i, 1);
                        const int pos = lane - 16;
                        if (pos >= 0) {
                            if (pos == r)      { best_d = dn; best_i = tile + j0 + ubase + 2 * src; }
                            else if (pos > r)  { best_d = pd; best_i = pi; }
                        }
                        thrB = __shfl_sync(FULLM, best_d, 31);
                    }
                }
            }
        }
    }
    const int q = qbase + (lane >> 4);
    g_idx[q * KNN + (lane & 15)] = best_i;
}

// ---------------- xq/xk/xv = x @ {Wq,Wk,Wv} ---------------------------------
__global__ void __launch_bounds__(256)
qkv_gemm_kernel(const float* __restrict__ x,
                const float* __restrict__ Wq,
                const float* __restrict__ Wk,
                const float* __restrict__ Wv) {
    __shared__ __align__(16) float Ws[CF * CF];
    __shared__ __align__(16) float xs[CF * CF];
    const float* W = (blockIdx.y == 0) ? Wq : ((blockIdx.y == 1) ? Wk : Wv);
    float* out = (blockIdx.y == 0) ? g_xq : ((blockIdx.y == 1) ? g_xk : g_xv);

    const int row0 = blockIdx.x * 64;
    const int tid  = threadIdx.y * 64 + threadIdx.x;
    for (int f = tid; f < CF * CF; f += 256) {
        Ws[f] = W[f];
        xs[f] = x[row0 * CF + f];
    }
    __syncthreads();

    const int c  = threadIdx.x;
    const int r0 = threadIdx.y * 16;
    float acc[16];
#pragma unroll
    for (int r = 0; r < 16; r++) acc[r] = 0.0f;

    const float4* xsv = reinterpret_cast<const float4*>(xs);
    for (int j4 = 0; j4 < 16; j4++) {
        float w0 = Ws[(4 * j4 + 0) * CF + c];
        float w1 = Ws[(4 * j4 + 1) * CF + c];
        float w2 = Ws[(4 * j4 + 2) * CF + c];
        float w3 = Ws[(4 * j4 + 3) * CF + c];
#pragma unroll
        for (int r = 0; r < 16; r++) {
            float4 xv = xsv[(r0 + r) * 16 + j4];
            acc[r] = fmaf(xv.x, w0, acc[r]);
            acc[r] = fmaf(xv.y, w1, acc[r]);
            acc[r] = fmaf(xv.z, w2, acc[r]);
            acc[r] = fmaf(xv.w, w3, acc[r]);
        }
    }
#pragma unroll
    for (int r = 0; r < 16; r++) out[(row0 + r0 + r) * CF + c] = acc[r];
}

// ---------------- PPF angle helper ------------------------------------------
__device__ __forceinline__ float angle3(float ux, float uy, float uz,
                                        float vx, float vy, float vz) {
    float cx = uy * vz - uz * vy;
    float cy = uz * vx - ux * vz;
    float cz = ux * vy - uy * vx;
    float cn = sqrtf(cx * cx + cy * cy + cz * cz + 1e-9f);
    float dt = ux * vx + uy * vy + uz * vz;
    return atan2f(cn, dt);
}

// ---------------- Fused: PPF -> pe MLP -> attention -> Wo -> LN -> relu ------
// 2 points per block, 128 threads. pe1 transposed; pe2 split by NEIGHBOR-half:
// warp-in-point w handles k in [8w, 8w+8) for all 64 channels (lane owns
// channel pair 2l, 2l+1), halving the broadcast LDS traffic per point.
__global__ void __launch_bounds__(128, 8)
fused_attn_kernel(const float* __restrict__ p,
                  const float* __restrict__ x,
                  const float* __restrict__ normals,
                  const float* __restrict__ Wo,
                  const float* __restrict__ w1, const float* __restrict__ b1,
                  const float* __restrict__ w2, const float* __restrict__ b2,
                  const float* __restrict__ ln_g, const float* __restrict__ ln_b,
                  float* __restrict__ out) {
    const int t128 = threadIdx.x;
    const int pt   = t128 >> 6;
    const int tid  = t128 & 63;
    const int n    = blockIdx.x * PPB + pt;

    __shared__ int   idx_s[PPB][KNN];
    __shared__ __align__(16) float ppf_s[PPB][KNN][4];
    __shared__ __align__(16) float pe1t[PPB][CF][KNN];   // transposed, 64B rows
    __shared__ __align__(16) float k_s[PPB][KNN][CF];
    __shared__ __align__(16) float v_s[PPB][KNN][CF];
    __shared__ __align__(16) float q_s[PPB][CF];
    __shared__ __align__(16) float o_s[PPB][CF];
    __shared__ float attn_s[PPB][NH * KNN];
    __shared__ float red_s[4][2];

    if (tid < KNN) idx_s[pt][tid] = g_idx[n * KNN + tid];
    q_s[pt][tid] = g_xq[n * CF + tid];
    __syncthreads();

    // PPF features: 64 tasks per point = (neighbor k, feature which)
    {
        const int k     = tid & 15;
        const int which = tid >> 4;
        const int j = idx_s[pt][k];
        float px = p[3 * n], py = p[3 * n + 1], pz = p[3 * n + 2];
        float dx = p[3 * j] - px, dy = p[3 * j + 1] - py, dz = p[3 * j + 2] - pz;
        float ncx = normals[3 * n], ncy = normals[3 * n + 1], ncz = normals[3 * n + 2];
        float nrx = normals[3 * j], nry = normals[3 * j + 1], nrz = normals[3 * j + 2];
        float ux = (which == 1) ? nrx : ncx;
        float uy = (which == 1) ? nry : ncy;
        float uz = (which == 1) ? nrz : ncz;
        float vx = (which == 2) ? nrx : dx;
        float vy = (which == 2) ? nry : dy;
        float vz = (which == 2) ? nrz : dz;
        float a = angle3(ux, uy, uz, vx, vy, vz);
        float dist = sqrtf(fmaf(dx, dx, fmaf(dy, dy, dz * dz)) + 1e-9f);
        ppf_s[pt][k][which] = (which == 3) ? dist : a;
    }
    __syncthreads();

    // pe layer 1, written transposed: pe1t[tid][k] (k rotated to soften conflicts)
    {
        float w0 = __ldg(&w1[0 * CF + tid]);
        float wa = __ldg(&w1[1 * CF + tid]);
        float wb = __ldg(&w1[2 * CF + tid]);
        float wc = __ldg(&w1[3 * CF + tid]);
        float bb = __ldg(&b1[tid]);
#pragma unroll
        for (int i = 0; i < KNN; i++) {
            const int k = (i + tid) & 15;
            float4 pf = *reinterpret_cast<const float4*>(&ppf_s[pt][k][0]);
            float v = bb;
            v = fmaf(pf.x, w0, v);
            v = fmaf(pf.y, wa, v);
            v = fmaf(pf.z, wb, v);
            v = fmaf(pf.w, wc, v);
            pe1t[pt][tid][k] = fmaxf(v, 0.0f);
        }
    }
    __syncthreads();

    // pe layer 2, k-split: warp-in-point handles k in [8w, 8w+8), all channels.
    // Lane owns channels (2l, 2l+1); acc2[ch][kp] packs k-pair (kbase+2kp, +1).
    {
        const int wip   = (t128 >> 5) & 1;
        const int l     = t128 & 31;
        const int c0    = 2 * l;
        const int kbase = 8 * wip;

        unsigned long long acc2[2][4];
        {
            float2 bb2 = *reinterpret_cast<const float2*>(&b2[c0]);
            unsigned long long bp0, bp1;
            PACK2(bp0, __float_as_uint(bb2.x), __float_as_uint(bb2.x));
            PACK2(bp1, __float_as_uint(bb2.y), __float_as_uint(bb2.y));
#pragma unroll
            for (int kp = 0; kp < 4; kp++) { acc2[0][kp] = bp0; acc2[1][kp] = bp1; }
        }
#pragma unroll 4
        for (int j = 0; j < CF; j++) {
            const ulonglong2* row =
                reinterpret_cast<const ulonglong2*>(&pe1t[pt][j][kbase]);
            ulonglong2 r0 = row[0];   // k: kbase..kbase+3
            ulonglong2 r1 = row[1];   // k: kbase+4..kbase+7
            float2 w = *reinterpret_cast<const float2*>(&w2[j * CF + c0]);
            unsigned long long wp0, wp1;
            PACK2(wp0, __float_as_uint(w.x), __float_as_uint(w.x));
            PACK2(wp1, __float_as_uint(w.y), __float_as_uint(w.y));
            FMA2(acc2[0][0], r0.x, wp0, acc2[0][0]);
            FMA2(acc2[0][1], r0.y, wp0, acc2[0][1]);
            FMA2(acc2[0][2], r1.x, wp0, acc2[0][2]);
            FMA2(acc2[0][3], r1.y, wp0, acc2[0][3]);
            FMA2(acc2[1][0], r0.x, wp1, acc2[1][0]);
            FMA2(acc2[1][1], r0.y, wp1, acc2[1][1]);
            FMA2(acc2[1][2], r1.x, wp1, acc2[1][2]);
            FMA2(acc2[1][3], r1.y, wp1, acc2[1][3]);
        }
        // unpack + gather xk/xv (float2 over channel pair), build k/v tiles
#pragma unroll
        for (int kp = 0; kp < 4; kp++) {
            unsigned lo0, hi0, lo1, hi1;
            UNPACK2(lo0, hi0, acc2[0][kp]);   // (pe[k][c0], pe[k+1][c0])
            UNPACK2(lo1, hi1, acc2[1][kp]);   // (pe[k][c1], pe[k+1][c1])
            const int k0 = kbase + 2 * kp;
            const int k1 = k0 + 1;
            const int j0 = idx_s[pt][k0];
            const int j1 = idx_s[pt][k1];
            float2 gk0 = *reinterpret_cast<const float2*>(&g_xk[j0 * CF + c0]);
            float2 gv0 = *reinterpret_cast<const float2*>(&g_xv[j0 * CF + c0]);
            float2 gk1 = *reinterpret_cast<const float2*>(&g_xk[j1 * CF + c0]);
            float2 gv1 = *reinterpret_cast<const float2*>(&g_xv[j1 * CF + c0]);
            float a0c0 = __uint_as_float(lo0), a1c0 = __uint_as_float(hi0);
            float a0c1 = __uint_as_float(lo1), a1c1 = __uint_as_float(hi1);
            *reinterpret_cast<float2*>(&k_s[pt][k0][c0]) =
                make_float2(gk0.x + a0c0, gk0.y + a0c1);
            *reinterpret_cast<float2*>(&v_s[pt][k0][c0]) =
                make_float2(gv0.x + a0c0, gv0.y + a0c1);
            *reinterpret_cast<float2*>(&k_s[pt][k1][c0]) =
                make_float2(gk1.x + a1c0, gk1.y + a1c1);
            *reinterpret_cast<float2*>(&v_s[pt][k1][c0]) =
                make_float2(gv1.x + a1c0, gv1.y + a1c1);
        }
    }
    __syncthreads();

    // attention: thread = (head h, neighbor kk) within its point
    {
        const int h  = tid >> 4;
        const int kk = tid & 15;
        float logit = 0.0f;
        const float4* kv = reinterpret_cast<const float4*>(&k_s[pt][kk][h * DHD]);
        const float4* qv = reinterpret_cast<const float4*>(&q_s[pt][h * DHD]);
#pragma unroll
        for (int d4 = 0; d4 < 4; d4++) {
            float4 kq = kv[d4];
            float4 qq = qv[d4];
            logit = fmaf(qq.x, kq.x, logit);
            logit = fmaf(qq.y, kq.y, logit);
            logit = fmaf(qq.z, kq.z, logit);
            logit = fmaf(qq.w, kq.w, logit);
        }
        logit *= 0.25f;  // 1/sqrt(16)

        float m = logit;
#pragma unroll
        for (int s = 8; s >= 1; s >>= 1)
            m = fmaxf(m, __shfl_xor_sync(FULLM, m, s, 16));
        float e = __expf(logit - m);
        float ssum = e;
#pragma unroll
        for (int s = 8; s >= 1; s >>= 1)
            ssum += __shfl_xor_sync(FULLM, ssum, s, 16);
        attn_s[pt][tid] = e / ssum;
    }
    __syncthreads();

    // out[c] = sum_k attn[h][k] * v[k][c],  c = h*16 + d
    {
        float o = 0.0f;
        const int hb = tid & ~15;
#pragma unroll
        for (int k = 0; k < KNN; k++)
            o = fmaf(attn_s[pt][hb + k], v_s[pt][k][tid], o);
        o_s[pt][tid] = o;
    }
    __syncthreads();

    // y = o @ Wo
    float y = 0.0f;
    {
        const float4* ov = reinterpret_cast<const float4*>(&o_s[pt][0]);
        for (int j4 = 0; j4 < 16; j4++) {
            float4 o4 = ov[j4];
            y = fmaf(o4.x, __ldg(&Wo[(4 * j4 + 0) * CF + tid]), y);
            y = fmaf(o4.y, __ldg(&Wo[(4 * j4 + 1) * CF + tid]), y);
            y = fmaf(o4.z, __ldg(&Wo[(4 * j4 + 2) * CF + tid]), y);
            y = fmaf(o4.w, __ldg(&Wo[(4 * j4 + 3) * CF + tid]), y);
        }
    }

    // LayerNorm (biased var), residual, relu
    float s1 = y, s2 = y * y;
#pragma unroll
    for (int s = 16; s >= 1; s >>= 1) {
        s1 += __shfl_xor_sync(FULLM, s1, s);
        s2 += __shfl_xor_sync(FULLM, s2, s);
    }
    const int wrp = t128 >> 5;
    if ((t128 & 31) == 0) {
        red_s[wrp][0] = s1;
        red_s[wrp][1] = s2;
    }
    __syncthreads();
    float S1 = red_s[2 * pt][0] + red_s[2 * pt + 1][0];
    float S2 = red_s[2 * pt][1] + red_s[2 * pt + 1][1];
    float mu  = S1 * (1.0f / 64.0f);
    float var = S2 * (1.0f / 64.0f) - mu * mu;
    float nrm = (y - mu) * rsqrtf(var + 1e-5f);
    float res = fmaf(nrm, __ldg(&ln_g[tid]), __ldg(&ln_b[tid])) + x[n * CF + tid];
    out[n * CF + tid] = fmaxf(res, 0.0f);
}

// ---------------- launch -----------------------------------------------------
extern "C" void kernel_launch(void* const* d_in, const int* in_sizes, int n_in,
                              void* d_out, int out_size) {
    (void)in_sizes; (void)n_in; (void)out_size;
    const float* p       = (const float*)d_in[0];
    const float* x       = (const float*)d_in[1];
    const float* normals = (const float*)d_in[2];
    const float* Wq      = (const float*)d_in[3];
    const float* Wk      = (const float*)d_in[4];
    const float* Wv      = (const float*)d_in[5];
    const float* Wo      = (const float*)d_in[6];
    const float* w1      = (const float*)d_in[7];
    const float* b1      = (const float*)d_in[8];
    const float* w2      = (const float*)d_in[9];
    const float* b2      = (const float*)d_in[10];
    const float* ln_g    = (const float*)d_in[11];
    const float* ln_b    = (const float*)d_in[12];
    float* out = (float*)d_out;

    knn_kernel<<<NPTS / 16, 256>>>(p);
    qkv_gemm_kernel<<<dim3(NPTS / 64, 3), dim3(64, 4)>>>(x, Wq, Wk, Wv);
    fused_attn_kernel<<<NPTS / PPB, 128>>>(p, x, normals, Wo, w1, b1, w2, b2,
                                           ln_g, ln_b, out);
}